// round 1
// baseline (speedup 1.0000x reference)
#include <cuda_runtime.h>
#include <math.h>
#include <stdint.h>

#define N_NODES 50000
#define N_EDGES 800000
#define IN_F    256
#define OUT_F   64
#define HEADS   4
#define HO      (HEADS * OUT_F)   // 256
#define NEG_SLOPE 0.2f

// ---------------- scratch (static device globals; no runtime alloc) --------
__device__ float g_h[(size_t)N_NODES * HO];        // 51.2 MB projected features
__device__ float g_attn_src[N_NODES * HEADS];      // [n][h]
__device__ float g_attn_dst[N_NODES * HEADS];
__device__ float g_e[(size_t)N_EDGES * HEADS];     // [e][h] scores then exp
__device__ float g_denom[N_NODES * HEADS];         // [n][h]
__device__ int   g_max_bits;                       // global max (float bits)

// ---------------- kernel 0: init ------------------------------------------
__global__ void init_kernel() {
    int i = blockIdx.x * blockDim.x + threadIdx.x;
    if (i == 0) g_max_bits = 0xFF800000; // -inf
    if (i < N_NODES * HEADS) g_denom[i] = 0.0f;
}

// ---------------- kernel 1: h = x @ W (per head) ---------------------------
#define BM 64
#define BN 64
#define BK 32

__global__ void __launch_bounds__(256) gemm_kernel(const float* __restrict__ x,
                                                   const float* __restrict__ W) {
    __shared__ __align__(16) float As[BK][BM + 4]; // [k][m], +4 pad keeps 16B align
    __shared__ __align__(16) float Bs[BK][BN];     // [k][n]

    const int m0   = blockIdx.x * BM;
    const int head = blockIdx.y;                   // BN == OUT_F, tile == head
    const float* Wh = W + (size_t)head * IN_F * OUT_F;

    const int t  = threadIdx.x;
    const int tx = t & 15;
    const int ty = t >> 4;

    float acc[4][4] = {};

    for (int k0 = 0; k0 < IN_F; k0 += BK) {
        // A tile: 64 rows x 32 k, coalesced float4 along k, transposed into As
        #pragma unroll
        for (int i = 0; i < 2; i++) {
            int idx = t + i * 256;          // 0..511
            int m   = idx >> 3;
            int kk  = (idx & 7) << 2;
            float4 v = make_float4(0.f, 0.f, 0.f, 0.f);
            int gm = m0 + m;
            if (gm < N_NODES)
                v = *(const float4*)(x + (size_t)gm * IN_F + k0 + kk);
            As[kk + 0][m] = v.x; As[kk + 1][m] = v.y;
            As[kk + 2][m] = v.z; As[kk + 3][m] = v.w;
        }
        // B tile: Bs[k][n] = Wh[(k0+k)*64 + n] (contiguous per k)
        #pragma unroll
        for (int i = 0; i < 2; i++) {
            int idx = t + i * 256;
            int k   = idx >> 4;
            int n   = (idx & 15) << 2;
            *(float4*)&Bs[k][n] = *(const float4*)(Wh + (size_t)(k0 + k) * OUT_F + n);
        }
        __syncthreads();

        #pragma unroll
        for (int k = 0; k < BK; k++) {
            float4 a4 = *(const float4*)&As[k][ty << 2];
            float4 b4 = *(const float4*)&Bs[k][tx << 2];
            float a[4] = {a4.x, a4.y, a4.z, a4.w};
            float b[4] = {b4.x, b4.y, b4.z, b4.w};
            #pragma unroll
            for (int i = 0; i < 4; i++)
                #pragma unroll
                for (int j = 0; j < 4; j++)
                    acc[i][j] = fmaf(a[i], b[j], acc[i][j]);
        }
        __syncthreads();
    }

    #pragma unroll
    for (int i = 0; i < 4; i++) {
        int gm = m0 + (ty << 2) + i;
        if (gm < N_NODES) {
            float4 v = make_float4(acc[i][0], acc[i][1], acc[i][2], acc[i][3]);
            *(float4*)(g_h + (size_t)gm * HO + head * OUT_F + (tx << 2)) = v;
        }
    }
}

// ---------------- kernel 2: per-node attention logits ----------------------
// one warp per (node, head); 64-dot via float2 per lane + shfl reduce
__global__ void attn_kernel(const float* __restrict__ a_src,
                            const float* __restrict__ a_dst) {
    int gw   = (blockIdx.x * blockDim.x + threadIdx.x) >> 5;
    int lane = threadIdx.x & 31;
    if (gw >= N_NODES * HEADS) return;
    int n = gw >> 2;        // / HEADS
    int h = gw & 3;         // % HEADS

    const float2* hv = (const float2*)(g_h + (size_t)n * HO + h * OUT_F);
    const float2* as = (const float2*)(a_src + h * OUT_F);
    const float2* ad = (const float2*)(a_dst + h * OUT_F);
    float2 v = hv[lane];
    float2 s2 = as[lane];
    float2 d2 = ad[lane];
    float s = v.x * s2.x + v.y * s2.y;
    float d = v.x * d2.x + v.y * d2.y;
    #pragma unroll
    for (int o = 16; o; o >>= 1) {
        s += __shfl_xor_sync(0xFFFFFFFFu, s, o);
        d += __shfl_xor_sync(0xFFFFFFFFu, d, o);
    }
    if (lane == 0) {
        g_attn_src[n * HEADS + h] = s;
        g_attn_dst[n * HEADS + h] = d;
    }
}

// ---------------- kernel 3: edge scores + global max -----------------------
__device__ __forceinline__ float leaky(float v) {
    return v >= 0.0f ? v : NEG_SLOPE * v;
}

__device__ void atomic_max_float(int* addr, float value) {
    int old = *addr;
    while (__int_as_float(old) < value) {
        int assumed = old;
        old = atomicCAS(addr, assumed, __float_as_int(value));
        if (old == assumed) break;
    }
}

__global__ void edge_score_kernel(const int* __restrict__ edge_index,
                                  const float* __restrict__ ew) {
    int e = blockIdx.x * blockDim.x + threadIdx.x;
    float local = -INFINITY;
    if (e < N_EDGES) {
        int src = edge_index[e];
        int dst = edge_index[N_EDGES + e];
        float w = ew[e];
        float4 as = *(const float4*)(g_attn_src + src * 4);
        float4 ad = *(const float4*)(g_attn_dst + dst * 4);
        float4 r;
        r.x = leaky(as.x + ad.x) * w;
        r.y = leaky(as.y + ad.y) * w;
        r.z = leaky(as.z + ad.z) * w;
        r.w = leaky(as.w + ad.w) * w;
        *(float4*)(g_e + (size_t)e * 4) = r;
        local = fmaxf(fmaxf(r.x, r.y), fmaxf(r.z, r.w));
    }
    #pragma unroll
    for (int o = 16; o; o >>= 1)
        local = fmaxf(local, __shfl_xor_sync(0xFFFFFFFFu, local, o));
    if ((threadIdx.x & 31) == 0 && local > -INFINITY)
        atomic_max_float(&g_max_bits, local);
}

// ---------------- kernel 4: exp + segment-sum denominator ------------------
__global__ void edge_exp_kernel(const int* __restrict__ edge_index) {
    int e = blockIdx.x * blockDim.x + threadIdx.x;
    if (e >= N_EDGES) return;
    float m = __int_as_float(g_max_bits);
    int dst = edge_index[N_EDGES + e];
    float4 r = *(const float4*)(g_e + (size_t)e * 4);
    r.x = __expf(r.x - m);
    r.y = __expf(r.y - m);
    r.z = __expf(r.z - m);
    r.w = __expf(r.w - m);
    *(float4*)(g_e + (size_t)e * 4) = r;
    float* dn = g_denom + (size_t)dst * 4;
    asm volatile("red.global.add.v4.f32 [%0], {%1, %2, %3, %4};"
                 :: "l"(dn), "f"(r.x), "f"(r.y), "f"(r.z), "f"(r.w) : "memory");
}

// ---------------- kernel 5: weighted scatter-add ----------------------------
// one warp per edge: 32 lanes x 2 float4 = 256 floats (all 4 heads)
__global__ void __launch_bounds__(256) scatter_kernel(const int* __restrict__ edge_index,
                                                      float* __restrict__ out) {
    int gw   = (blockIdx.x * blockDim.x + threadIdx.x) >> 5;
    int lane = threadIdx.x & 31;
    if (gw >= N_EDGES) return;
    int e   = gw;
    int src = edge_index[e];
    int dst = edge_index[N_EDGES + e];

    float4 ee = *(const float4*)(g_e + (size_t)e * 4);      // broadcast load
    float4 dn = *(const float4*)(g_denom + (size_t)dst * 4);
    float a0 = ee.x / (dn.x + 1e-10f);
    float a1 = ee.y / (dn.y + 1e-10f);
    float a2 = ee.z / (dn.z + 1e-10f);
    float a3 = ee.w / (dn.w + 1e-10f);

    const float4* hsrc = (const float4*)(g_h + (size_t)src * HO);
    float4*       od   = (float4*)(out + (size_t)dst * HO);

    // j=0: float4 chunks 0..31  -> heads 0 (lane<16) / 1 (lane>=16)
    // j=1: float4 chunks 32..63 -> heads 2 (lane<16) / 3 (lane>=16)
    {
        float al = (lane < 16) ? a0 : a1;
        float4 v = hsrc[lane];
        v.x *= al; v.y *= al; v.z *= al; v.w *= al;
        asm volatile("red.global.add.v4.f32 [%0], {%1, %2, %3, %4};"
                     :: "l"(od + lane), "f"(v.x), "f"(v.y), "f"(v.z), "f"(v.w) : "memory");
    }
    {
        float al = (lane < 16) ? a2 : a3;
        float4 v = hsrc[lane + 32];
        v.x *= al; v.y *= al; v.z *= al; v.w *= al;
        asm volatile("red.global.add.v4.f32 [%0], {%1, %2, %3, %4};"
                     :: "l"(od + lane + 32), "f"(v.x), "f"(v.y), "f"(v.z), "f"(v.w) : "memory");
    }
}

// ---------------- launch ----------------------------------------------------
extern "C" void kernel_launch(void* const* d_in, const int* in_sizes, int n_in,
                              void* d_out, int out_size) {
    const float* x     = (const float*)d_in[0];
    const int*   eidx  = (const int*)  d_in[1];
    const float* ew    = (const float*)d_in[2];
    const float* W     = (const float*)d_in[3];
    const float* a_src = (const float*)d_in[4];
    const float* a_dst = (const float*)d_in[5];
    float* out = (float*)d_out;

    // zero output (accumulated via atomics) and small state
    cudaMemsetAsync(out, 0, (size_t)out_size * sizeof(float));
    init_kernel<<<(N_NODES * HEADS + 255) / 256, 256>>>();

    dim3 ggrid((N_NODES + BM - 1) / BM, HEADS);
    gemm_kernel<<<ggrid, 256>>>(x, W);

    int attn_warps = N_NODES * HEADS;
    attn_kernel<<<(attn_warps * 32 + 255) / 256, 256>>>(a_src, a_dst);

    edge_score_kernel<<<(N_EDGES + 255) / 256, 256>>>(eidx, ew);
    edge_exp_kernel<<<(N_EDGES + 255) / 256, 256>>>(eidx);

    // one warp per edge
    scatter_kernel<<<(N_EDGES * 32 + 255) / 256, 256>>>(eidx, out);
}

// round 2
// speedup vs baseline: 1.2710x; 1.2710x over previous
#include <cuda_runtime.h>
#include <math.h>
#include <stdint.h>

#define N_NODES 50000
#define N_EDGES 800000
#define IN_F    256
#define OUT_F   64
#define HEADS   4
#define HO      (HEADS * OUT_F)   // 256
#define NEG_SLOPE 0.2f

#define SCAN_BLK 256
#define NSCAN ((N_NODES + SCAN_BLK - 1) / SCAN_BLK)   // 196

// ---------------- scratch (static device globals) --------------------------
__device__ float g_h[(size_t)N_NODES * HO];        // 51.2 MB projected features
__device__ float g_attn_src[N_NODES * HEADS];
__device__ float g_attn_dst[N_NODES * HEADS];
__device__ float g_e[(size_t)N_EDGES * HEADS];     // [e][h] raw scores
__device__ int   g_max_bits;                       // global max (float bits)
// CSR-by-dst machinery
__device__ int g_deg[N_NODES];
__device__ int g_scan[N_NODES];
__device__ int g_bsum[NSCAN];
__device__ int g_rowstart[N_NODES];
__device__ int g_ptr[N_NODES];
__device__ int g_sorted_src[N_EDGES];
__device__ int g_sorted_eid[N_EDGES];

// ---------------- kernel 0: init ------------------------------------------
__global__ void init_kernel() {
    int i = blockIdx.x * blockDim.x + threadIdx.x;
    if (i == 0) g_max_bits = 0xFF800000; // -inf
    if (i < N_NODES) g_deg[i] = 0;
}

// ---------------- kernel 1: h = x @ W_combined (all heads fused) -----------
// C[50000, 256] = x[50000, 256] @ Wc[256, 256], Wc[k][h*64+o] = W[h][k][o]
#define GBM 128
#define GBN 128
#define GBK 8
#define KTILES (IN_F / GBK)   // 32

__global__ void __launch_bounds__(256) gemm_kernel(const float* __restrict__ x,
                                                   const float* __restrict__ W) {
    __shared__ __align__(16) float As[2][GBK][GBM + 4];
    __shared__ __align__(16) float Bs[2][GBK][GBN];

    const int m0 = blockIdx.x * GBM;
    const int n0 = blockIdx.y * GBN;
    const int t  = threadIdx.x;

    // A-load mapping: thread -> (row, 4-wide k chunk)
    const int am = t >> 1;            // 0..127
    const int ak = (t & 1) << 2;      // 0 or 4
    const int gm = m0 + am;
    const bool a_ok = (gm < N_NODES);
    const float* Aptr = x + (size_t)gm * IN_F + ak;

    // B-load mapping: thread -> (k row, 4-wide n chunk); resolve head once
    const int bk = t >> 5;            // 0..7
    const int bn = (t & 31) << 2;     // 0..124
    const int nb = n0 + bn;
    const float* Bptr = W + (size_t)(nb >> 6) * IN_F * OUT_F + (nb & 63); // + k*64

    float4 rA, rB;
    // prefetch k-tile 0
    rA = a_ok ? *(const float4*)(Aptr) : make_float4(0.f, 0.f, 0.f, 0.f);
    rB = *(const float4*)(Bptr + (size_t)bk * OUT_F);
    As[0][ak + 0][am] = rA.x; As[0][ak + 1][am] = rA.y;
    As[0][ak + 2][am] = rA.z; As[0][ak + 3][am] = rA.w;
    *(float4*)&Bs[0][bk][bn] = rB;
    __syncthreads();

    const int tx = t & 15;
    const int ty = t >> 4;
    float acc[8][8] = {};

    for (int kt = 0; kt < KTILES; kt++) {
        const int cur = kt & 1;
        if (kt + 1 < KTILES) {
            const int k0 = (kt + 1) * GBK;
            rA = a_ok ? *(const float4*)(Aptr + k0) : make_float4(0.f, 0.f, 0.f, 0.f);
            rB = *(const float4*)(Bptr + (size_t)(k0 + bk) * OUT_F);
        }
        #pragma unroll
        for (int k = 0; k < GBK; k++) {
            float4 a0 = *(const float4*)&As[cur][k][ty << 2];
            float4 a1 = *(const float4*)&As[cur][k][(ty << 2) + 64];
            float4 b0 = *(const float4*)&Bs[cur][k][tx << 2];
            float4 b1 = *(const float4*)&Bs[cur][k][(tx << 2) + 64];
            float a[8] = {a0.x, a0.y, a0.z, a0.w, a1.x, a1.y, a1.z, a1.w};
            float b[8] = {b0.x, b0.y, b0.z, b0.w, b1.x, b1.y, b1.z, b1.w};
            #pragma unroll
            for (int i = 0; i < 8; i++)
                #pragma unroll
                for (int j = 0; j < 8; j++)
                    acc[i][j] = fmaf(a[i], b[j], acc[i][j]);
        }
        if (kt + 1 < KTILES) {
            const int nxt = cur ^ 1;
            As[nxt][ak + 0][am] = rA.x; As[nxt][ak + 1][am] = rA.y;
            As[nxt][ak + 2][am] = rA.z; As[nxt][ak + 3][am] = rA.w;
            *(float4*)&Bs[nxt][bk][bn] = rB;
            __syncthreads();
        }
    }

    #pragma unroll
    for (int i = 0; i < 8; i++) {
        int row = m0 + ((i < 4) ? (ty << 2) + i : 60 + (ty << 2) + i);
        if (row < N_NODES) {
            float* dst = g_h + (size_t)row * HO + n0;
            *(float4*)(dst + (tx << 2))      = make_float4(acc[i][0], acc[i][1], acc[i][2], acc[i][3]);
            *(float4*)(dst + (tx << 2) + 64) = make_float4(acc[i][4], acc[i][5], acc[i][6], acc[i][7]);
        }
    }
}

// ---------------- kernel 2: per-node attention logits ----------------------
__global__ void attn_kernel(const float* __restrict__ a_src,
                            const float* __restrict__ a_dst) {
    int gw   = (blockIdx.x * blockDim.x + threadIdx.x) >> 5;
    int lane = threadIdx.x & 31;
    if (gw >= N_NODES * HEADS) return;
    int n = gw >> 2;
    int h = gw & 3;

    const float2* hv = (const float2*)(g_h + (size_t)n * HO + h * OUT_F);
    const float2* as = (const float2*)(a_src + h * OUT_F);
    const float2* ad = (const float2*)(a_dst + h * OUT_F);
    float2 v = hv[lane];
    float2 s2 = as[lane];
    float2 d2 = ad[lane];
    float s = v.x * s2.x + v.y * s2.y;
    float d = v.x * d2.x + v.y * d2.y;
    #pragma unroll
    for (int o = 16; o; o >>= 1) {
        s += __shfl_xor_sync(0xFFFFFFFFu, s, o);
        d += __shfl_xor_sync(0xFFFFFFFFu, d, o);
    }
    if (lane == 0) {
        g_attn_src[n * HEADS + h] = s;
        g_attn_dst[n * HEADS + h] = d;
    }
}

// ---------------- kernel 3: edge scores + global max + dst histogram -------
__device__ __forceinline__ float leaky(float v) {
    return v >= 0.0f ? v : NEG_SLOPE * v;
}

__device__ void atomic_max_float(int* addr, float value) {
    int old = *addr;
    while (__int_as_float(old) < value) {
        int assumed = old;
        old = atomicCAS(addr, assumed, __float_as_int(value));
        if (old == assumed) break;
    }
}

__global__ void edge_score_kernel(const int* __restrict__ edge_index,
                                  const float* __restrict__ ew) {
    int e = blockIdx.x * blockDim.x + threadIdx.x;
    float local = -INFINITY;
    if (e < N_EDGES) {
        int src = edge_index[e];
        int dst = edge_index[N_EDGES + e];
        atomicAdd(&g_deg[dst], 1);
        float w = ew[e];
        float4 as = *(const float4*)(g_attn_src + src * 4);
        float4 ad = *(const float4*)(g_attn_dst + dst * 4);
        float4 r;
        r.x = leaky(as.x + ad.x) * w;
        r.y = leaky(as.y + ad.y) * w;
        r.z = leaky(as.z + ad.z) * w;
        r.w = leaky(as.w + ad.w) * w;
        *(float4*)(g_e + (size_t)e * 4) = r;
        local = fmaxf(fmaxf(r.x, r.y), fmaxf(r.z, r.w));
    }
    #pragma unroll
    for (int o = 16; o; o >>= 1)
        local = fmaxf(local, __shfl_xor_sync(0xFFFFFFFFu, local, o));
    if ((threadIdx.x & 31) == 0 && local > -INFINITY)
        atomic_max_float(&g_max_bits, local);
}

// ---------------- kernels 4-6: exclusive scan of g_deg ---------------------
__global__ void scan1_kernel() {
    __shared__ int s[SCAN_BLK];
    int t = threadIdx.x;
    int i = blockIdx.x * SCAN_BLK + t;
    int v = (i < N_NODES) ? g_deg[i] : 0;
    s[t] = v;
    __syncthreads();
    #pragma unroll
    for (int off = 1; off < SCAN_BLK; off <<= 1) {
        int tmp = (t >= off) ? s[t - off] : 0;
        __syncthreads();
        if (t >= off) s[t] += tmp;
        __syncthreads();
    }
    if (i < N_NODES) g_scan[i] = s[t];
    if (t == SCAN_BLK - 1) g_bsum[blockIdx.x] = s[t];
}

__global__ void scan2_kernel() {   // 1 block, NSCAN <= 256
    __shared__ int s[SCAN_BLK];
    int t = threadIdx.x;
    int v = (t < NSCAN) ? g_bsum[t] : 0;
    s[t] = v;
    __syncthreads();
    #pragma unroll
    for (int off = 1; off < SCAN_BLK; off <<= 1) {
        int tmp = (t >= off) ? s[t - off] : 0;
        __syncthreads();
        if (t >= off) s[t] += tmp;
        __syncthreads();
    }
    if (t < NSCAN) g_bsum[t] = s[t] - v;   // exclusive
}

__global__ void scan3_kernel() {
    int i = blockIdx.x * SCAN_BLK + threadIdx.x;
    if (i < N_NODES) {
        int rs = g_scan[i] - g_deg[i] + g_bsum[blockIdx.x];
        g_rowstart[i] = rs;
        g_ptr[i] = rs;
    }
}

// ---------------- kernel 7: bucket edges by dst -----------------------------
__global__ void sort_kernel(const int* __restrict__ edge_index) {
    int e = blockIdx.x * blockDim.x + threadIdx.x;
    if (e >= N_EDGES) return;
    int src = edge_index[e];
    int dst = edge_index[N_EDGES + e];
    int pos = atomicAdd(&g_ptr[dst], 1);
    g_sorted_src[pos] = src;
    g_sorted_eid[pos] = e;
}

// ---------------- kernel 8: gather-aggregate (exp + softmax + matvec) -------
// one warp per dst node; accumulates all 4 heads (256 floats) in registers
__global__ void __launch_bounds__(256) aggregate_kernel(float* __restrict__ out) {
    int n    = (blockIdx.x * blockDim.x + threadIdx.x) >> 5;
    int lane = threadIdx.x & 31;
    if (n >= N_NODES) return;

    const int start = g_rowstart[n];
    const int deg   = g_deg[n];
    const float m   = __int_as_float(g_max_bits);

    float4 acc0 = make_float4(0.f, 0.f, 0.f, 0.f);
    float4 acc1 = make_float4(0.f, 0.f, 0.f, 0.f);
    float4 ds   = make_float4(0.f, 0.f, 0.f, 0.f);

    for (int i = 0; i < deg; i++) {
        int idx = start + i;
        int src = __ldg(&g_sorted_src[idx]);   // broadcast
        int eid = __ldg(&g_sorted_eid[idx]);
        float4 sc = *(const float4*)(g_e + (size_t)eid * 4);
        float4 ee;
        ee.x = __expf(sc.x - m);
        ee.y = __expf(sc.y - m);
        ee.z = __expf(sc.z - m);
        ee.w = __expf(sc.w - m);
        ds.x += ee.x; ds.y += ee.y; ds.z += ee.z; ds.w += ee.w;

        float alo = (lane < 16) ? ee.x : ee.y;   // heads 0/1
        float ahi = (lane < 16) ? ee.z : ee.w;   // heads 2/3
        const float4* hs = (const float4*)(g_h + (size_t)src * HO);
        float4 v0 = hs[lane];
        float4 v1 = hs[lane + 32];
        acc0.x = fmaf(v0.x, alo, acc0.x);
        acc0.y = fmaf(v0.y, alo, acc0.y);
        acc0.z = fmaf(v0.z, alo, acc0.z);
        acc0.w = fmaf(v0.w, alo, acc0.w);
        acc1.x = fmaf(v1.x, ahi, acc1.x);
        acc1.y = fmaf(v1.y, ahi, acc1.y);
        acc1.z = fmaf(v1.z, ahi, acc1.z);
        acc1.w = fmaf(v1.w, ahi, acc1.w);
    }

    float dlo = 1.0f / (((lane < 16) ? ds.x : ds.y) + 1e-10f);
    float dhi = 1.0f / (((lane < 16) ? ds.z : ds.w) + 1e-10f);
    float4* od = (float4*)(out + (size_t)n * HO);
    od[lane]      = make_float4(acc0.x * dlo, acc0.y * dlo, acc0.z * dlo, acc0.w * dlo);
    od[lane + 32] = make_float4(acc1.x * dhi, acc1.y * dhi, acc1.z * dhi, acc1.w * dhi);
}

// ---------------- launch ----------------------------------------------------
extern "C" void kernel_launch(void* const* d_in, const int* in_sizes, int n_in,
                              void* d_out, int out_size) {
    const float* x     = (const float*)d_in[0];
    const int*   eidx  = (const int*)  d_in[1];
    const float* ew    = (const float*)d_in[2];
    const float* W     = (const float*)d_in[3];
    const float* a_src = (const float*)d_in[4];
    const float* a_dst = (const float*)d_in[5];
    float* out = (float*)d_out;

    init_kernel<<<NSCAN, SCAN_BLK>>>();

    dim3 ggrid((N_NODES + GBM - 1) / GBM, HO / GBN);
    gemm_kernel<<<ggrid, 256>>>(x, W);

    attn_kernel<<<(N_NODES * HEADS * 32 + 255) / 256, 256>>>(a_src, a_dst);

    edge_score_kernel<<<(N_EDGES + 255) / 256, 256>>>(eidx, ew);

    scan1_kernel<<<NSCAN, SCAN_BLK>>>();
    scan2_kernel<<<1, SCAN_BLK>>>();
    scan3_kernel<<<NSCAN, SCAN_BLK>>>();

    sort_kernel<<<(N_EDGES + 255) / 256, 256>>>(eidx);

    aggregate_kernel<<<(N_NODES * 32 + 255) / 256, 256>>>(out);
}